// round 12
// baseline (speedup 1.0000x reference)
#include <cuda_runtime.h>
#include <cuda_fp16.h>
#include <math.h>

// Problem constants
#define NB    8
#define C     528
#define CV4   (C/4)          // 132 uint2 groups (4 fp16 channels each)
#define T     16
#define HH    32
#define WW    32
#define R     1024
#define OUTB  8
#define SR    2
#define SCALE (1.0f/16.0f)

#define MAXSUP 144
#define ROIS   8             // rois per block in fused kernel

// NHWC feature scratch in fp16: [b][y][x][c]
__device__ __half g_feat_h[NB * HH * WW * C];

// ---------------------------------------------------------------------------
// Kernel 1: temporal mean + NCHW -> NHWC transpose, float4 loads (R11 best).
// grid: (NB*HH, 17), block: 256.
// ---------------------------------------------------------------------------
__global__ __launch_bounds__(256)
void mean_t_transpose_kernel(const float* __restrict__ x)
{
    __shared__ float tile[32][37];

    const int bid = blockIdx.x;        // b*32 + y
    const int b   = bid >> 5;
    const int y   = bid & 31;
    const int cchunk = blockIdx.y;

    const int tid = threadIdx.x;
    const int xq  = tid & 7;
    const int cl  = tid >> 3;

    const int c = cchunk * 32 + cl;
    if (c < C) {
        const float4* p = (const float4*)
            (x + (((size_t)(b * C + c) * T) * HH + y) * WW + xq * 4);
        float4 s0 = make_float4(0.f, 0.f, 0.f, 0.f);
        float4 s1 = make_float4(0.f, 0.f, 0.f, 0.f);
        #pragma unroll
        for (int t = 0; t < T; t += 2) {
            const float4 v0 = __ldcs(p + (size_t)t       * (HH * WW / 4));
            const float4 v1 = __ldcs(p + (size_t)(t + 1) * (HH * WW / 4));
            s0.x += v0.x; s0.y += v0.y; s0.z += v0.z; s0.w += v0.w;
            s1.x += v1.x; s1.y += v1.y; s1.z += v1.z; s1.w += v1.w;
        }
        const int xb = xq * 4;
        tile[cl][xb + 0] = (s0.x + s1.x) * (1.0f / T);
        tile[cl][xb + 1] = (s0.y + s1.y) * (1.0f / T);
        tile[cl][xb + 2] = (s0.z + s1.z) * (1.0f / T);
        tile[cl][xb + 3] = (s0.w + s1.w) * (1.0f / T);
    }
    __syncthreads();

    const int cw = tid & 31;
    const int xw = tid >> 5;
    const int c2 = cchunk * 32 + cw;
    if (c2 < C) {
        #pragma unroll
        for (int xs = 0; xs < 4; xs++) {
            const int xx = xs * 8 + xw;
            g_feat_h[(((size_t)(b * HH + y)) * WW + xx) * C + c2] =
                __float2half(tile[cw][xx]);
        }
    }
}

// ---------------------------------------------------------------------------
// Kernel 2: fused ROI pooling (flat support list) + MLP, 8 rois per block.
// grid: R/8 = 128, block: 512.
// ---------------------------------------------------------------------------
__global__ __launch_bounds__(512)
void roi_mlp_kernel(const float* __restrict__ bbox,
                    const float* __restrict__ W1, const float* __restrict__ b1,
                    const float* __restrict__ W2, const float* __restrict__ b2,
                    const float* __restrict__ W3, const float* __restrict__ b3,
                    float* __restrict__ out)
{
    __shared__ float sAx[ROIS][32], sAy[ROIS][32];
    __shared__ int   sB[ROIS];
    __shared__ int   sXlo[ROIS], sNx[ROIS], sYlo[ROIS], sNy[ROIS], sN[ROIS];
    __shared__ int   sOff[ROIS][MAXSUP];
    __shared__ float sW[ROIS][MAXSUP];
    __shared__ float sPooled[ROIS][C];
    __shared__ float sH1[ROIS][128];
    __shared__ float sPart2[2][ROIS][32];
    __shared__ float sH2[ROIS][32];

    const int tid  = threadIdx.x;
    const int roi0 = blockIdx.x * ROIS;

    // Phase A1: per-bin axis weights. 512 threads = 8 rois x 2 axes x 32 bins.
    // warp = (r, axis), lane = bin. Deterministic (each bin sums its samples).
    {
        const int r    = tid >> 6;
        const int axis = (tid >> 5) & 1;
        const int bin  = tid & 31;
        const float* bb = bbox + (roi0 + r) * 5;
        if (axis == 0 && bin == 0) sB[r] = (int)bb[0];

        const float lo_c = bb[1 + axis] * SCALE - 0.5f;
        const float hi_c = bb[3 + axis] * SCALE - 0.5f;
        const float step = (hi_c - lo_c) * (1.0f / (OUTB * SR));

        float w = 0.f;
        #pragma unroll
        for (int s = 0; s < 16; s++) {
            const float v = lo_c + ((float)s + 0.5f) * step;
            const bool valid = (v >= -1.0f) && (v <= 32.0f);
            float vc   = fminf(fmaxf(v, 0.0f), 31.0f);
            float lof  = floorf(vc);
            float frac = vc - lof;
            int ilo = (int)lof;
            int ihi = min(ilo + 1, 31);
            if (valid) {
                if (ilo == bin) w += 1.0f - frac;
                if (ihi == bin) w += frac;
            }
        }
        if (axis) sAy[r][bin] = w; else sAx[r][bin] = w;

        unsigned m = __ballot_sync(0xFFFFFFFF, w != 0.f);
        if (bin == 0) {
            int lo, n;
            if (m == 0u) { lo = 0; n = 0; }
            else { lo = __ffs(m) - 1; n = (31 - __clz(m)) - lo + 1; }
            if (axis) { sYlo[r] = lo; sNy[r] = n; }
            else      { sXlo[r] = lo; sNx[r] = n; }
        }
    }
    __syncthreads();

    // Phase A2: flatten support lists. 64 threads per roi.
    {
        const int r   = tid >> 6;
        const int lid = tid & 63;
        const int nx = sNx[r], ny = sNy[r];
        int n = nx * ny;
        if (n > MAXSUP) n = MAXSUP;
        if (lid == 0) sN[r] = n;
        for (int i = lid; i < n; i += 64) {
            const int iy = i / nx;
            const int ix = i - iy * nx;
            const int y  = sYlo[r] + iy;
            const int xp = sXlo[r] + ix;
            sOff[r][i] = (y * WW + xp) * CV4;
            sW[r][i]   = sAy[r][y] * sAx[r][xp] * (1.0f / 256.0f);
        }
    }
    __syncthreads();

    // Phase B: flat gather. 1056 (roi, c4) units over 512 threads.
    for (int u = tid; u < ROIS * CV4; u += 512) {
        const int r  = u / CV4;
        const int c4 = u - r * CV4;
        const int n  = sN[r];
        const uint2* base = (const uint2*)g_feat_h
                          + (size_t)sB[r] * (HH * WW * CV4) + c4;
        const int*   off = sOff[r];
        const float* wv  = sW[r];

        float4 acc = make_float4(0.f, 0.f, 0.f, 0.f);
        #pragma unroll 4
        for (int i = 0; i < n; i++) {
            const float w   = wv[i];
            const uint2 raw = base[off[i]];
            const float2 f01 = __half22float2(*(const __half2*)&raw.x);
            const float2 f23 = __half22float2(*(const __half2*)&raw.y);
            acc.x = fmaf(w, f01.x, acc.x);
            acc.y = fmaf(w, f01.y, acc.y);
            acc.z = fmaf(w, f23.x, acc.z);
            acc.w = fmaf(w, f23.y, acc.w);
        }
        ((float4*)&sPooled[r][0])[c4] = acc;
    }
    __syncthreads();

    // Phase C: layer 1 (528 -> 128, relu), register-tiled.
    // 16 warps = 2 roi-groups x 8 warps. Within a warp:
    //   part = lane>>2 (8 c-parts of 66), jq = lane&3, j4 = w8*4 + jq.
    // Each thread: 4 roi accumulators (its group), float4 over j.
    {
        const int w    = tid >> 5;
        const int lane = tid & 31;
        const int rg   = w >> 3;              // roi group 0..1
        const int w8   = w & 7;
        const int part = lane >> 2;
        const int jq   = lane & 3;
        const int j4   = w8 * 4 + jq;
        const int c0   = part * 66;

        const float4* W1_4 = (const float4*)W1;   // [c][32]

        float4 a[4];
        #pragma unroll
        for (int r = 0; r < 4; r++) a[r] = make_float4(0.f, 0.f, 0.f, 0.f);

        #pragma unroll 2
        for (int c = c0; c < c0 + 66; c++) {
            const float4 wv = W1_4[c * 32 + j4];
            #pragma unroll
            for (int r = 0; r < 4; r++) {
                const float p = sPooled[rg * 4 + r][c];
                a[r].x = fmaf(p, wv.x, a[r].x);
                a[r].y = fmaf(p, wv.y, a[r].y);
                a[r].z = fmaf(p, wv.z, a[r].z);
                a[r].w = fmaf(p, wv.w, a[r].w);
            }
        }

        #pragma unroll
        for (int off = 4; off <= 16; off <<= 1) {
            #pragma unroll
            for (int r = 0; r < 4; r++) {
                a[r].x += __shfl_xor_sync(0xFFFFFFFF, a[r].x, off);
                a[r].y += __shfl_xor_sync(0xFFFFFFFF, a[r].y, off);
                a[r].z += __shfl_xor_sync(0xFFFFFFFF, a[r].z, off);
                a[r].w += __shfl_xor_sync(0xFFFFFFFF, a[r].w, off);
            }
        }

        if (part == 0) {
            const float4 bb = ((const float4*)b1)[j4];
            #pragma unroll
            for (int r = 0; r < 4; r++) {
                float4 h;
                h.x = fmaxf(a[r].x + bb.x, 0.f);
                h.y = fmaxf(a[r].y + bb.y, 0.f);
                h.z = fmaxf(a[r].z + bb.z, 0.f);
                h.w = fmaxf(a[r].w + bb.w, 0.f);
                ((float4*)&sH1[rg * 4 + r][0])[j4] = h;
            }
        }
    }
    __syncthreads();

    // Phase D: layer 2 (128 -> 32). 512 threads = 2 k-parts x 8 rois x 32 j.
    {
        const int part = tid >> 8;            // 0..1 (64 k each)
        const int r    = (tid >> 5) & 7;
        const int j    = tid & 31;
        const int k0 = part * 64;
        const float* h = sH1[r];
        float a0 = 0.f, a1 = 0.f;
        #pragma unroll
        for (int k = k0; k < k0 + 64; k += 2) {
            a0 = fmaf(h[k],     W2[(k)     * 32 + j], a0);
            a1 = fmaf(h[k + 1], W2[(k + 1) * 32 + j], a1);
        }
        sPart2[part][r][j] = a0 + a1;
    }
    __syncthreads();
    if (tid < ROIS * 32) {
        const int r = tid >> 5;
        const int j = tid & 31;
        sH2[r][j] = sPart2[0][r][j] + sPart2[1][r][j] + b2[j];
    }
    __syncthreads();

    // Phase E: layer 3 + sigmoid. 8 warps, one roi each.
    if (tid < ROIS * 32) {
        const int r    = tid >> 5;
        const int lane = tid & 31;
        float v = sH2[r][lane] * W3[lane];
        #pragma unroll
        for (int off = 16; off > 0; off >>= 1)
            v += __shfl_xor_sync(0xFFFFFFFF, v, off);
        if (lane == 0)
            out[roi0 + r] = 1.0f / (1.0f + expf(-(v + b3[0])));
    }
}

// ---------------------------------------------------------------------------
extern "C" void kernel_launch(void* const* d_in, const int* in_sizes, int n_in,
                              void* d_out, int out_size)
{
    const float* x    = (const float*)d_in[0];
    const float* bbox = (const float*)d_in[1];
    const float* W1   = (const float*)d_in[2];
    const float* b1   = (const float*)d_in[3];
    const float* W2   = (const float*)d_in[4];
    const float* b2   = (const float*)d_in[5];
    const float* W3   = (const float*)d_in[6];
    const float* b3   = (const float*)d_in[7];
    float* out = (float*)d_out;

    dim3 g1(NB * HH, 17);
    mean_t_transpose_kernel<<<g1, 256>>>(x);

    roi_mlp_kernel<<<R / ROIS, 512>>>(bbox, W1, b1, W2, b2, W3, b3, out);
}

// round 13
// speedup vs baseline: 1.2750x; 1.2750x over previous
#include <cuda_runtime.h>
#include <cuda_fp16.h>
#include <math.h>

// Problem constants
#define NB    8
#define C     528
#define CV4   (C/4)          // 132 uint2 groups (4 fp16 channels each)
#define T     16
#define HH    32
#define WW    32
#define R     1024
#define OUTB  8
#define SR    2
#define SCALE (1.0f/16.0f)

#define MAXSUP 144
#define NQ     4             // support-list quarters (independent gather streams)
#define PBLK   544           // pool block: 4 groups x 136 lanes (132 active)

// NHWC feature scratch in fp16: [b][y][x][c]
__device__ __half g_feat_h[NB * HH * WW * C];
// pooled scratch fp32: [roi][c]
__device__ float g_pooled[R * C];

// ---------------------------------------------------------------------------
// Kernel 1: temporal mean + NCHW -> NHWC transpose, float4 loads.
// grid: (NB*HH, 17), block: 256.  (R11 version: 44.2us, 80.9% DRAM)
// ---------------------------------------------------------------------------
__global__ __launch_bounds__(256)
void mean_t_transpose_kernel(const float* __restrict__ x)
{
    __shared__ float tile[32][37];

    const int bid = blockIdx.x;        // b*32 + y
    const int b   = bid >> 5;
    const int y   = bid & 31;
    const int cchunk = blockIdx.y;

    const int tid = threadIdx.x;
    const int xq  = tid & 7;
    const int cl  = tid >> 3;

    const int c = cchunk * 32 + cl;
    if (c < C) {
        const float4* p = (const float4*)
            (x + (((size_t)(b * C + c) * T) * HH + y) * WW + xq * 4);
        float4 s0 = make_float4(0.f, 0.f, 0.f, 0.f);
        float4 s1 = make_float4(0.f, 0.f, 0.f, 0.f);
        #pragma unroll
        for (int t = 0; t < T; t += 2) {
            const float4 v0 = __ldcs(p + (size_t)t       * (HH * WW / 4));
            const float4 v1 = __ldcs(p + (size_t)(t + 1) * (HH * WW / 4));
            s0.x += v0.x; s0.y += v0.y; s0.z += v0.z; s0.w += v0.w;
            s1.x += v1.x; s1.y += v1.y; s1.z += v1.z; s1.w += v1.w;
        }
        const int xb = xq * 4;
        tile[cl][xb + 0] = (s0.x + s1.x) * (1.0f / T);
        tile[cl][xb + 1] = (s0.y + s1.y) * (1.0f / T);
        tile[cl][xb + 2] = (s0.z + s1.z) * (1.0f / T);
        tile[cl][xb + 3] = (s0.w + s1.w) * (1.0f / T);
    }
    __syncthreads();

    const int cw = tid & 31;
    const int xw = tid >> 5;
    const int c2 = cchunk * 32 + cw;
    if (c2 < C) {
        #pragma unroll
        for (int xs = 0; xs < 4; xs++) {
            const int xx = xs * 8 + xw;
            g_feat_h[(((size_t)(b * HH + y)) * WW + xx) * C + c2] =
                __float2half(tile[cw][xx]);
        }
    }
}

// ---------------------------------------------------------------------------
// Kernel 2: ROI pooling, flat support list SPLIT 4 WAYS for parallelism.
// grid: R, block: 544. Thread (q, lane): q = tid/136 sums quarter q of the
// support list for channel-group lane; deterministic (q0+q1)+(q2+q3) reduce.
// ---------------------------------------------------------------------------
__global__ __launch_bounds__(PBLK)
void roi_pool_kernel(const float* __restrict__ bbox)
{
    __shared__ float  sAx[32], sAy[32];
    __shared__ int    sB, sXlo, sNx, sYlo, sNy, sN;
    __shared__ int    sOff[MAXSUP];     // pixel offset in uint2 units
    __shared__ float  sW[MAXSUP];
    __shared__ float4 sQ[NQ][CV4];      // per-quarter partials (8.4 KB)

    const int tid = threadIdx.x;
    const int roi = blockIdx.x;

    // Phase A1: per-bin axis weights (warp0 = x, warp1 = y), deterministic
    if (tid < 64) {
        const int axis = tid >> 5;
        const int bin  = tid & 31;
        const float* bb = bbox + roi * 5;
        if (tid == 0) sB = (int)bb[0];

        const float lo_c = bb[1 + axis] * SCALE - 0.5f;
        const float hi_c = bb[3 + axis] * SCALE - 0.5f;
        const float step = (hi_c - lo_c) * (1.0f / (OUTB * SR));

        float w = 0.f;
        #pragma unroll
        for (int s = 0; s < 16; s++) {
            const float v = lo_c + ((float)s + 0.5f) * step;
            const bool valid = (v >= -1.0f) && (v <= 32.0f);
            float vc   = fminf(fmaxf(v, 0.0f), 31.0f);
            float lof  = floorf(vc);
            float frac = vc - lof;
            int ilo = (int)lof;
            int ihi = min(ilo + 1, 31);
            if (valid) {
                if (ilo == bin) w += 1.0f - frac;
                if (ihi == bin) w += frac;
            }
        }
        if (axis) sAy[bin] = w; else sAx[bin] = w;

        unsigned m = __ballot_sync(0xFFFFFFFF, w != 0.f);
        if (bin == 0) {
            int lo, n;
            if (m == 0u) { lo = 0; n = 0; }
            else { lo = __ffs(m) - 1; n = (31 - __clz(m)) - lo + 1; }
            if (axis) { sYlo = lo; sNy = n; }
            else      { sXlo = lo; sNx = n; }
        }
    }
    __syncthreads();

    // Phase A2: flatten support into (offset, weight) list
    {
        const int nx = sNx, ny = sNy;
        int n = nx * ny;
        if (n > MAXSUP) n = MAXSUP;
        if (tid == 0) sN = n;
        for (int i = tid; i < n; i += PBLK) {
            const int iy = i / nx;
            const int ix = i - iy * nx;
            const int y  = sYlo + iy;
            const int xp = sXlo + ix;
            sOff[i] = (y * WW + xp) * CV4;
            sW[i]   = sAy[y] * sAx[xp] * (1.0f / 256.0f);
        }
    }
    __syncthreads();

    // Phase B: gather — each quarter-group sums its slice of the support
    {
        const int q    = tid / 136;     // 0..3
        const int lane = tid - q * 136; // 0..135, active if < CV4
        if (lane < CV4) {
            const int n  = sN;
            const int nq = (n + NQ - 1) / NQ;
            const int i0 = q * nq;
            const int i1 = min(i0 + nq, n);

            const uint2* base = (const uint2*)g_feat_h
                              + (size_t)sB * (HH * WW * CV4) + lane;

            float4 acc = make_float4(0.f, 0.f, 0.f, 0.f);
            #pragma unroll 4
            for (int i = i0; i < i1; i++) {
                const float w   = sW[i];
                const uint2 raw = base[sOff[i]];
                const float2 f01 = __half22float2(*(const __half2*)&raw.x);
                const float2 f23 = __half22float2(*(const __half2*)&raw.y);
                acc.x = fmaf(w, f01.x, acc.x);
                acc.y = fmaf(w, f01.y, acc.y);
                acc.z = fmaf(w, f23.x, acc.z);
                acc.w = fmaf(w, f23.y, acc.w);
            }
            sQ[q][lane] = acc;
        }
    }
    __syncthreads();

    // Phase C: deterministic quarter reduction + store
    if (tid < CV4) {
        const float4 a0 = sQ[0][tid];
        const float4 a1 = sQ[1][tid];
        const float4 a2 = sQ[2][tid];
        const float4 a3 = sQ[3][tid];
        float4 acc;
        acc.x = (a0.x + a1.x) + (a2.x + a3.x);
        acc.y = (a0.y + a1.y) + (a2.y + a3.y);
        acc.z = (a0.z + a1.z) + (a2.z + a3.z);
        acc.w = (a0.w + a1.w) + (a2.w + a3.w);
        ((float4*)g_pooled)[(size_t)roi * CV4 + tid] = acc;
    }
}

// ---------------------------------------------------------------------------
// Kernel 3: MLP 528 -> 128 (relu) -> 32 -> 1 (sigmoid), 8 rois per block.
// grid: R/8 = 128, block: 256. Layer 1 register-tiled GEMM.  (R9 version)
// ---------------------------------------------------------------------------
#define MR 8

__global__ __launch_bounds__(256)
void mlp_kernel(const float* __restrict__ W1, const float* __restrict__ b1,
                const float* __restrict__ W2, const float* __restrict__ b2,
                const float* __restrict__ W3, const float* __restrict__ b3,
                float* __restrict__ out)
{
    __shared__ float sPooled[MR][C];
    __shared__ float sH1[MR][128];
    __shared__ float sH2[MR][32];

    const int tid  = threadIdx.x;
    const int roi0 = blockIdx.x * MR;

    {
        const float4* gp4 = (const float4*)g_pooled + (size_t)roi0 * CV4;
        float4* sp4 = (float4*)&sPooled[0][0];
        #pragma unroll
        for (int u = tid; u < MR * CV4; u += 256)
            sp4[u] = gp4[u];
    }
    __syncthreads();

    // Layer 1
    {
        const int lane = tid & 31;
        const int w    = tid >> 5;            // warp 0..7
        const int part = lane >> 2;           // 0..7 (c-part, 66 each)
        const int jq   = lane & 3;
        const int j4   = w * 4 + jq;          // float4 index over j (0..31)
        const int c0   = part * 66;

        const float4* W1_4 = (const float4*)W1;   // [c][32]

        float4 a[MR];
        #pragma unroll
        for (int r = 0; r < MR; r++) a[r] = make_float4(0.f, 0.f, 0.f, 0.f);

        #pragma unroll 2
        for (int c = c0; c < c0 + 66; c++) {
            const float4 wv = W1_4[c * 32 + j4];
            #pragma unroll
            for (int r = 0; r < MR; r++) {
                const float p = sPooled[r][c];
                a[r].x = fmaf(p, wv.x, a[r].x);
                a[r].y = fmaf(p, wv.y, a[r].y);
                a[r].z = fmaf(p, wv.z, a[r].z);
                a[r].w = fmaf(p, wv.w, a[r].w);
            }
        }

        #pragma unroll
        for (int off = 4; off <= 16; off <<= 1) {
            #pragma unroll
            for (int r = 0; r < MR; r++) {
                a[r].x += __shfl_xor_sync(0xFFFFFFFF, a[r].x, off);
                a[r].y += __shfl_xor_sync(0xFFFFFFFF, a[r].y, off);
                a[r].z += __shfl_xor_sync(0xFFFFFFFF, a[r].z, off);
                a[r].w += __shfl_xor_sync(0xFFFFFFFF, a[r].w, off);
            }
        }

        if (part == 0) {
            const float4 bb = ((const float4*)b1)[j4];
            #pragma unroll
            for (int r = 0; r < MR; r++) {
                float4 h;
                h.x = fmaxf(a[r].x + bb.x, 0.f);
                h.y = fmaxf(a[r].y + bb.y, 0.f);
                h.z = fmaxf(a[r].z + bb.z, 0.f);
                h.w = fmaxf(a[r].w + bb.w, 0.f);
                ((float4*)&sH1[r][0])[j4] = h;
            }
        }
    }
    __syncthreads();

    // Layer 2
    {
        const int r = tid >> 5;
        const int j = tid & 31;
        const float* h = sH1[r];
        float a0 = 0.f, a1 = 0.f;
        #pragma unroll
        for (int k = 0; k < 128; k += 2) {
            a0 = fmaf(h[k],     W2[(k)     * 32 + j], a0);
            a1 = fmaf(h[k + 1], W2[(k + 1) * 32 + j], a1);
        }
        sH2[r][j] = a0 + a1 + b2[j];
    }
    __syncthreads();

    // Layer 3 + sigmoid
    {
        const int r    = tid >> 5;
        const int lane = tid & 31;
        float v = sH2[r][lane] * W3[lane];
        #pragma unroll
        for (int off = 16; off > 0; off >>= 1)
            v += __shfl_xor_sync(0xFFFFFFFF, v, off);
        if (lane == 0)
            out[roi0 + r] = 1.0f / (1.0f + expf(-(v + b3[0])));
    }
}

// ---------------------------------------------------------------------------
extern "C" void kernel_launch(void* const* d_in, const int* in_sizes, int n_in,
                              void* d_out, int out_size)
{
    const float* x    = (const float*)d_in[0];
    const float* bbox = (const float*)d_in[1];
    const float* W1   = (const float*)d_in[2];
    const float* b1   = (const float*)d_in[3];
    const float* W2   = (const float*)d_in[4];
    const float* b2   = (const float*)d_in[5];
    const float* W3   = (const float*)d_in[6];
    const float* b3   = (const float*)d_in[7];
    float* out = (float*)d_out;

    dim3 g1(NB * HH, 17);
    mean_t_transpose_kernel<<<g1, 256>>>(x);

    roi_pool_kernel<<<R, PBLK>>>(bbox);

    mlp_kernel<<<R / MR, 256>>>(W1, b1, W2, b2, W3, b3, out);
}